// round 12
// baseline (speedup 1.0000x reference)
#include <cuda_runtime.h>
#include <cuda_fp16.h>

#define NCHAN 256
#define NPTS  49
#define NTILE_L5 32
#define NTILE_L4 128
#define NTILE_L3 512
#define NTILE_L2 2048
#define NTP (NTILE_L5 + NTILE_L4 + NTILE_L3 + NTILE_L2)   // 2720

// fp16 HWC scratch for image 0 of levels 2..5, channel-interleaved:
// slot(pix, l, k) = pix*256 + 8*l + k  holds channel 32*k + l.  44.6 MB.
#define OFF_L2 0
#define OFF_L3 (65536 * 256)
#define OFF_L4 (OFF_L3 + 16384 * 256)
#define OFF_L5 (OFF_L4 + 4096 * 256)
#define SCRATCH_ELEMS (OFF_L5 + 1024 * 256)
__device__ __align__(16) __half g_scratch[SCRATCH_ELEMS];

// per-level completed-tile counters, index = level-2
__device__ volatile int g_done[4];
__constant__ int c_need[4] = {NTILE_L2, NTILE_L3, NTILE_L4, NTILE_L5};

__global__ void reset_flags() {
    g_done[0] = 0; g_done[1] = 0; g_done[2] = 0; g_done[3] = 0;
}

struct PoolSmem {
    float sout[NCHAN * NPTS];
    int   oTL[NPTS], oTR[NPTS], oBL[NPTS], oBR[NPTS];
    float lx[NPTS], ly[NPTS], m[NPTS];
};
struct TposeSmem { float tile[256][33]; };

// ---- fused kernel: blocks [0,NTP) transpose tiles (L5,L4,L3,L2 order),
//      blocks [NTP, NTP+nrois) pool rois gated on per-level flags ----
__global__ __launch_bounds__(384, 3) void fused(const float* __restrict__ p2,
                                                const float* __restrict__ p3,
                                                const float* __restrict__ p4,
                                                const float* __restrict__ p5,
                                                const float* __restrict__ rois,
                                                float* __restrict__ out) {
    __shared__ __align__(16) char smem_raw[sizeof(PoolSmem)];
    int b   = blockIdx.x;
    int tid = threadIdx.x;

    if (b < NTP) {
        // ================= transpose tile =================
        TposeSmem& ts = *(TposeSmem*)smem_raw;
        const float* in;
        __half* op;
        int HW, lvl;
        if (b < NTILE_L5)                        { in = p5; op = g_scratch + OFF_L5; HW = 1024;  lvl = 5; }
        else if (b < NTILE_L5 + NTILE_L4)        { b -= NTILE_L5; in = p4; op = g_scratch + OFF_L4; HW = 4096;  lvl = 4; }
        else if (b < NTILE_L5 + NTILE_L4 + NTILE_L3) { b -= NTILE_L5 + NTILE_L4; in = p3; op = g_scratch + OFF_L3; HW = 16384; lvl = 3; }
        else                                     { b -= NTILE_L5 + NTILE_L4 + NTILE_L3; in = p2; op = g_scratch + OFF_L2; HW = 65536; lvl = 2; }

        int tx = tid & 31, ty = tid >> 5;   // 32 x 12
        int x = b * 32 + tx;
        for (int j = ty; j < 256; j += 12)
            ts.tile[j][tx] = __ldcs(in + j * HW + x);
        __syncthreads();

        int pbase = b * 32;
        for (int px = ty; px < 32; px += 12) {
            __half2 h01 = __floats2half2_rn(ts.tile[tx      ][px], ts.tile[tx + 32 ][px]);
            __half2 h23 = __floats2half2_rn(ts.tile[tx + 64 ][px], ts.tile[tx + 96 ][px]);
            __half2 h45 = __floats2half2_rn(ts.tile[tx + 128][px], ts.tile[tx + 160][px]);
            __half2 h67 = __floats2half2_rn(ts.tile[tx + 192][px], ts.tile[tx + 224][px]);
            uint4 v;
            v.x = *(unsigned*)&h01;
            v.y = *(unsigned*)&h23;
            v.z = *(unsigned*)&h45;
            v.w = *(unsigned*)&h67;
            *(uint4*)(op + (pbase + px) * NCHAN + 8 * tx) = v;
        }
        __syncthreads();
        if (tid == 0) {
            __threadfence();
            atomicAdd((int*)&g_done[lvl - 2], 1);
        }
        return;
    }

    // ================= pool roi =================
    PoolSmem& ps = *(PoolSmem*)smem_raw;
    int n = b - NTP;

    float rx1 = __ldg(rois + 4 * n + 0);
    float ry1 = __ldg(rois + 4 * n + 1);
    float rx2 = __ldg(rois + 4 * n + 2);
    float ry2 = __ldg(rois + 4 * n + 3);

    float area = (ry2 - ry1) * (rx2 - rx1);
    float lvlf = log2f(sqrtf(fmaxf(area, 0.0f)) / 224.0f);
    int level = (int)rintf(lvlf) + 4;          // half-even, matches jnp.round
    level = min(5, max(2, level));
    int W = 1024 >> level;                     // H == W

    if (tid < NPTS) {
        float scale = (float)(W - 1);
        float ny1 = ry1 * (1.0f / 1024.0f);
        float nx1 = rx1 * (1.0f / 1024.0f);
        float dy  = __fsub_rn(ry2 * (1.0f / 1024.0f), ny1);
        float dx  = __fsub_rn(rx2 * (1.0f / 1024.0f), nx1);

        int py = tid / 7;
        int px = tid - py * 7;

        float ty = (float)py / 6.0f;
        float ys = __fmul_rn(__fadd_rn(ny1, __fmul_rn(ty, dy)), scale);
        bool  vy = (ys >= 0.0f) && (ys <= scale);
        float ysc = fminf(fmaxf(ys, 0.0f), scale);
        int   y0  = (int)floorf(ysc);
        int   y1i = min(y0 + 1, W - 1);
        float ly  = __fsub_rn(ysc, (float)y0);

        float tx = (float)px / 6.0f;
        float xs = __fmul_rn(__fadd_rn(nx1, __fmul_rn(tx, dx)), scale);
        bool  vx = (xs >= 0.0f) && (xs <= scale);
        float xsc = fminf(fmaxf(xs, 0.0f), scale);
        int   x0  = (int)floorf(xsc);
        int   x1i = min(x0 + 1, W - 1);
        float lx  = __fsub_rn(xsc, (float)x0);

        ps.oTL[tid] = y0  * W + x0;
        ps.oTR[tid] = y0  * W + x1i;
        ps.oBL[tid] = y1i * W + x0;
        ps.oBR[tid] = y1i * W + x1i;
        ps.lx[tid] = lx;
        ps.ly[tid] = ly;
        ps.m[tid]  = (vy && vx) ? 1.0f : 0.0f;
    }

    // gate on this level's transpose tiles (thread 0 spins, others park at barrier)
    if (tid == 0) {
        int need = c_need[level - 2];
        while (g_done[level - 2] < need)
            __nanosleep(128);
        __threadfence();
    }
    __syncthreads();

    long obase = (long)n * (NCHAN * NPTS);
    const __half* fm = g_scratch +
        ((level == 2) ? OFF_L2 : (level == 3) ? OFF_L3 :
         (level == 4) ? OFF_L4 : OFF_L5);
    int warpid = tid >> 5;       // 0..11, pts stride 12
    int lane   = tid & 31;
    int lbias  = 8 * lane;

    #pragma unroll 4
    for (int pt = warpid; pt < NPTS; pt += 12) {
        uint4 tlq = __ldg((const uint4*)(fm + ps.oTL[pt] * NCHAN + lbias));
        uint4 trq = __ldg((const uint4*)(fm + ps.oTR[pt] * NCHAN + lbias));
        uint4 blq = __ldg((const uint4*)(fm + ps.oBL[pt] * NCHAN + lbias));
        uint4 brq = __ldg((const uint4*)(fm + ps.oBR[pt] * NCHAN + lbias));
        float lx = ps.lx[pt], ly = ps.ly[pt], m = ps.m[pt];

        const unsigned* tlw = (const unsigned*)&tlq;
        const unsigned* trw = (const unsigned*)&trq;
        const unsigned* blw = (const unsigned*)&blq;
        const unsigned* brw = (const unsigned*)&brq;
        #pragma unroll
        for (int j = 0; j < 4; j++) {          // half2 pair j -> k = 2j, 2j+1
            float2 tl = __half22float2(*(const __half2*)&tlw[j]);
            float2 tr = __half22float2(*(const __half2*)&trw[j]);
            float2 bl = __half22float2(*(const __half2*)&blw[j]);
            float2 br = __half22float2(*(const __half2*)&brw[j]);

            float topx = fmaf(tr.x - tl.x, lx, tl.x);
            float botx = fmaf(br.x - bl.x, lx, bl.x);
            ps.sout[((2 * j) * 32 + lane) * NPTS + pt] = fmaf(botx - topx, ly, topx) * m;

            float topy = fmaf(tr.y - tl.y, lx, tl.y);
            float boty = fmaf(br.y - bl.y, lx, bl.y);
            ps.sout[((2 * j + 1) * 32 + lane) * NPTS + pt] = fmaf(boty - topy, ly, topy) * m;
        }
    }
    __syncthreads();

    const float4* s4 = (const float4*)ps.sout;
    float4* o4 = (float4*)(out + obase);
    for (int i = tid; i < NCHAN * NPTS / 4; i += 384)
        __stcs(o4 + i, s4[i]);
}

extern "C" void kernel_launch(void* const* d_in, const int* in_sizes, int n_in,
                              void* d_out, int out_size) {
    const float* p2   = (const float*)d_in[0];
    const float* p3   = (const float*)d_in[1];
    const float* p4   = (const float*)d_in[2];
    const float* p5   = (const float*)d_in[3];
    const float* rois = (const float*)d_in[4];
    float* out = (float*)d_out;

    int nrois = in_sizes[4] / 4;   // B*R

    reset_flags<<<1, 1>>>();
    fused<<<NTP + nrois, 384>>>(p2, p3, p4, p5, rois, out);
}

// round 13
// speedup vs baseline: 1.1591x; 1.1591x over previous
#include <cuda_runtime.h>
#include <cuda_fp16.h>

#define NCHAN 256
#define NPTS  49

// fp16 HWC scratch for image 0 of levels 2..5, channel-interleaved:
// slot(pix, l, k) = pix*256 + 8*l + k  holds channel 32*k + l.  44.6 MB.
#define OFF_L2 0
#define OFF_L3 (65536 * 256)
#define OFF_L4 (OFF_L3 + 16384 * 256)
#define OFF_L5 (OFF_L4 + 4096 * 256)
#define SCRATCH_ELEMS (OFF_L5 + 1024 * 256)
__device__ __align__(16) __half g_scratch[SCRATCH_ELEMS];

// ---- CHW(fp32) -> interleaved-HWC(fp16) transpose tile body ----
__device__ __forceinline__ void tpose_tile(const float* __restrict__ in,
                                           __half* __restrict__ op,
                                           int HW, int b, int tid) {
    __shared__ float tile[256][33];
    int tx = tid & 31, ty = tid >> 5;  // 32 x 16
    int x = b * 32 + tx;
    #pragma unroll
    for (int j = ty; j < 256; j += 16)
        tile[j][tx] = __ldcs(in + j * HW + x);
    __syncthreads();

    int pbase = b * 32;
    #pragma unroll
    for (int px = ty; px < 32; px += 16) {
        __half2 h01 = __floats2half2_rn(tile[tx      ][px], tile[tx + 32 ][px]);
        __half2 h23 = __floats2half2_rn(tile[tx + 64 ][px], tile[tx + 96 ][px]);
        __half2 h45 = __floats2half2_rn(tile[tx + 128][px], tile[tx + 160][px]);
        __half2 h67 = __floats2half2_rn(tile[tx + 192][px], tile[tx + 224][px]);
        uint4 v;
        v.x = *(unsigned*)&h01;
        v.y = *(unsigned*)&h23;
        v.z = *(unsigned*)&h45;
        v.w = *(unsigned*)&h67;
        *(uint4*)(op + (pbase + px) * NCHAN + 8 * tx) = v;
    }
}

// levels 3,4,5: 512 + 128 + 32 = 672 blocks
__global__ __launch_bounds__(512) void tpose35(const float* __restrict__ p3,
                                               const float* __restrict__ p4,
                                               const float* __restrict__ p5) {
    int b = blockIdx.x;
    if (b < 512)      tpose_tile(p3, g_scratch + OFF_L3, 16384, b, threadIdx.x);
    else if (b < 640) tpose_tile(p4, g_scratch + OFF_L4, 4096,  b - 512, threadIdx.x);
    else              tpose_tile(p5, g_scratch + OFF_L5, 1024,  b - 640, threadIdx.x);
}

// level 2: 2048 blocks
__global__ __launch_bounds__(512) void tpose2(const float* __restrict__ p2) {
    tpose_tile(p2, g_scratch + OFF_L2, 65536, blockIdx.x, threadIdx.x);
}

// ---- pooling from fp16 interleaved scratch; want2 selects which rois to do ----
__global__ __launch_bounds__(384, 3) void roi_pool(const float* __restrict__ rois,
                                                   float* __restrict__ out,
                                                   int want2) {
    int n   = blockIdx.x;
    int tid = threadIdx.x;

    float rx1 = __ldg(rois + 4 * n + 0);
    float ry1 = __ldg(rois + 4 * n + 1);
    float rx2 = __ldg(rois + 4 * n + 2);
    float ry2 = __ldg(rois + 4 * n + 3);

    float area = (ry2 - ry1) * (rx2 - rx1);
    float lvlf = log2f(sqrtf(fmaxf(area, 0.0f)) / 224.0f);
    int level = (int)rintf(lvlf) + 4;          // half-even, matches jnp.round
    level = min(5, max(2, level));
    if ((level == 2) != (want2 != 0)) return;

    __shared__ __align__(16) float sout[NCHAN * NPTS];  // flat == output layout
    __shared__ int   s_oTL[NPTS], s_oTR[NPTS], s_oBL[NPTS], s_oBR[NPTS];
    __shared__ float s_lx[NPTS], s_ly[NPTS], s_m[NPTS];

    int W = 1024 >> level;                     // H == W

    if (tid < NPTS) {
        float scale = (float)(W - 1);
        float ny1 = ry1 * (1.0f / 1024.0f);
        float nx1 = rx1 * (1.0f / 1024.0f);
        float dy  = __fsub_rn(ry2 * (1.0f / 1024.0f), ny1);
        float dx  = __fsub_rn(rx2 * (1.0f / 1024.0f), nx1);

        int py = tid / 7;
        int px = tid - py * 7;

        float ty = (float)py / 6.0f;
        float ys = __fmul_rn(__fadd_rn(ny1, __fmul_rn(ty, dy)), scale);
        bool  vy = (ys >= 0.0f) && (ys <= scale);
        float ysc = fminf(fmaxf(ys, 0.0f), scale);
        int   y0  = (int)floorf(ysc);
        int   y1i = min(y0 + 1, W - 1);
        float ly  = __fsub_rn(ysc, (float)y0);

        float tx = (float)px / 6.0f;
        float xs = __fmul_rn(__fadd_rn(nx1, __fmul_rn(tx, dx)), scale);
        bool  vx = (xs >= 0.0f) && (xs <= scale);
        float xsc = fminf(fmaxf(xs, 0.0f), scale);
        int   x0  = (int)floorf(xsc);
        int   x1i = min(x0 + 1, W - 1);
        float lx  = __fsub_rn(xsc, (float)x0);

        s_oTL[tid] = y0  * W + x0;
        s_oTR[tid] = y0  * W + x1i;
        s_oBL[tid] = y1i * W + x0;
        s_oBR[tid] = y1i * W + x1i;
        s_lx[tid] = lx;
        s_ly[tid] = ly;
        s_m[tid]  = (vy && vx) ? 1.0f : 0.0f;
    }
    __syncthreads();

    long obase = (long)n * (NCHAN * NPTS);
    const __half* fm = g_scratch +
        ((level == 2) ? OFF_L2 : (level == 3) ? OFF_L3 :
         (level == 4) ? OFF_L4 : OFF_L5);
    int warpid = tid >> 5;       // 0..11, pts stride 12
    int lane   = tid & 31;
    int lbias  = 8 * lane;

    #pragma unroll 4
    for (int pt = warpid; pt < NPTS; pt += 12) {
        uint4 tlq = __ldg((const uint4*)(fm + s_oTL[pt] * NCHAN + lbias));
        uint4 trq = __ldg((const uint4*)(fm + s_oTR[pt] * NCHAN + lbias));
        uint4 blq = __ldg((const uint4*)(fm + s_oBL[pt] * NCHAN + lbias));
        uint4 brq = __ldg((const uint4*)(fm + s_oBR[pt] * NCHAN + lbias));
        float lx = s_lx[pt], ly = s_ly[pt], m = s_m[pt];

        const unsigned* tlw = (const unsigned*)&tlq;
        const unsigned* trw = (const unsigned*)&trq;
        const unsigned* blw = (const unsigned*)&blq;
        const unsigned* brw = (const unsigned*)&brq;
        #pragma unroll
        for (int j = 0; j < 4; j++) {          // half2 pair j -> k = 2j, 2j+1
            float2 tl = __half22float2(*(const __half2*)&tlw[j]);
            float2 tr = __half22float2(*(const __half2*)&trw[j]);
            float2 bl = __half22float2(*(const __half2*)&blw[j]);
            float2 br = __half22float2(*(const __half2*)&brw[j]);

            float topx = fmaf(tr.x - tl.x, lx, tl.x);
            float botx = fmaf(br.x - bl.x, lx, bl.x);
            sout[((2 * j) * 32 + lane) * NPTS + pt] = fmaf(botx - topx, ly, topx) * m;

            float topy = fmaf(tr.y - tl.y, lx, tl.y);
            float boty = fmaf(br.y - bl.y, lx, bl.y);
            sout[((2 * j + 1) * 32 + lane) * NPTS + pt] = fmaf(boty - topy, ly, topy) * m;
        }
    }
    __syncthreads();

    const float4* s4 = (const float4*)sout;
    float4* o4 = (float4*)(out + obase);
    for (int i = tid; i < NCHAN * NPTS / 4; i += 384)
        __stcs(o4 + i, s4[i]);
}

extern "C" void kernel_launch(void* const* d_in, const int* in_sizes, int n_in,
                              void* d_out, int out_size) {
    const float* p2   = (const float*)d_in[0];
    const float* p3   = (const float*)d_in[1];
    const float* p4   = (const float*)d_in[2];
    const float* p5   = (const float*)d_in[3];
    const float* rois = (const float*)d_in[4];
    float* out = (float*)d_out;

    int nrois = in_sizes[4] / 4;   // B*R

    // One-time host-side stream/event setup (host objects, no device memory).
    static cudaStream_t s2 = 0;
    static cudaEvent_t evFork = 0, evJoin = 0;
    if (s2 == 0) {
        cudaStreamCreateWithFlags(&s2, cudaStreamNonBlocking);
        cudaEventCreateWithFlags(&evFork, cudaEventDisableTiming);
        cudaEventCreateWithFlags(&evJoin, cudaEventDisableTiming);
    }

    // fork: chain B (level-2 transpose + level-2 rois) on s2
    cudaEventRecord(evFork, 0);
    cudaStreamWaitEvent(s2, evFork, 0);
    tpose2<<<2048, 512, 0, s2>>>(p2);
    roi_pool<<<nrois, 384, 0, s2>>>(rois, out, 1);
    cudaEventRecord(evJoin, s2);

    // chain A (levels 3-5) on the default stream
    tpose35<<<672, 512>>>(p3, p4, p5);
    roi_pool<<<nrois, 384>>>(rois, out, 0);

    // join
    cudaStreamWaitEvent(0, evJoin, 0);
}